// round 6
// baseline (speedup 1.0000x reference)
#include <cuda_runtime.h>
#include <cuda_fp16.h>
#include <stdint.h>

// ---------------- problem constants ----------------
#define N_USERS 100000
#define N_ITEMS 50000
#define NNODES  150000           // N_USERS + N_ITEMS
#define EMB_DIM 64
#define NNZ     6400000
#define BATCH   4096
#define N_LAYERS 3

#define HIST_T  (NNZ / 4)                 // int4 hist work items
#define INIT_T  (NNODES * EMB_DIM / 4)    // float4 init work items
#define SCAN_BLOCKS ((NNODES + 1 + 1023) / 1024)   // 147 (<= #SMs, all resident)

// ---------------- device scratch (static, allocation-free) ----------------
// Zero-init covers the FIRST call; k_cleanup re-zeroes g_rowptr / g_scan_pkt
// at the end of EVERY call so each call performs identical work.
__device__ int                         g_rowptr[NNODES + 1];
__device__ volatile unsigned long long g_scan_pkt[SCAN_BLOCKS]; // (flag<<32)|value
__device__ unsigned short              g_rank[NNZ];
__device__ int2                        g_edges[NNZ];            // {dst, val fp32 bits}
__device__ __half                      g_xh[N_LAYERS + 1][NNODES * EMB_DIM];

// ---------------- fused histogram (+rank) and x0 fp16 init -----------------
__global__ void k_hist_init(const int4* __restrict__ src4,
                            const float4* __restrict__ user_emb,
                            const float4* __restrict__ item_emb) {
    int t = blockIdx.x * blockDim.x + threadIdx.x;
    if (t < HIST_T) {
        int4 s = src4[t];
        ushort4 r;
        r.x = (unsigned short)atomicAdd(&g_rowptr[s.x + 1], 1);
        r.y = (unsigned short)atomicAdd(&g_rowptr[s.y + 1], 1);
        r.z = (unsigned short)atomicAdd(&g_rowptr[s.z + 1], 1);
        r.w = (unsigned short)atomicAdd(&g_rowptr[s.w + 1], 1);
        ((ushort4*)g_rank)[t] = r;
    } else {
        int i = t - HIST_T;
        if (i < INIT_T) {
            const int us = N_USERS * EMB_DIM / 4;
            float4 v = (i < us) ? user_emb[i] : item_emb[i - us];
            __half2 a = __floats2half2_rn(v.x, v.y);
            __half2 b = __floats2half2_rn(v.z, v.w);
            uint2 o;
            o.x = *reinterpret_cast<unsigned int*>(&a);
            o.y = *reinterpret_cast<unsigned int*>(&b);
            ((uint2*)&g_xh[0][0])[i] = o;
        }
    }
}

// ---------------- single-pass decoupled-lookback inclusive scan ------------
__global__ void __launch_bounds__(1024) k_scan() {
    __shared__ int warp_sums[32];
    __shared__ int s_prefix;
    const int lane = threadIdx.x & 31;
    const int wid  = threadIdx.x >> 5;
    const int b    = blockIdx.x;
    int idx = b * 1024 + (int)threadIdx.x;
    int v = (idx <= NNODES) ? g_rowptr[idx] : 0;

    int x = v;
#pragma unroll
    for (int off = 1; off < 32; off <<= 1) {
        int t = __shfl_up_sync(0xffffffffu, x, off);
        if (lane >= off) x += t;
    }
    if (lane == 31) warp_sums[wid] = x;
    __syncthreads();
    if (wid == 0) {
        int w = warp_sums[lane];
#pragma unroll
        for (int off = 1; off < 32; off <<= 1) {
            int t = __shfl_up_sync(0xffffffffu, w, off);
            if (lane >= off) w += t;
        }
        warp_sums[lane] = w;
    }
    __syncthreads();
    int incl = x + ((wid > 0) ? warp_sums[wid - 1] : 0);
    int block_total = warp_sums[31];

    if (threadIdx.x == 0) {
        if (b == 0) {
            g_scan_pkt[0] = (2ull << 32) | (unsigned int)block_total;
            s_prefix = 0;
        } else {
            g_scan_pkt[b] = (1ull << 32) | (unsigned int)block_total;
            int prefix = 0;
            int p = b - 1;
            while (true) {
                unsigned long long q;
                do { q = g_scan_pkt[p]; } while ((q >> 32) == 0ull);
                prefix += (int)(unsigned int)q;
                if ((q >> 32) == 2ull) break;
                p--;
            }
            g_scan_pkt[b] = (2ull << 32) | (unsigned int)(prefix + block_total);
            s_prefix = prefix;
        }
    }
    __syncthreads();
    if (idx <= NNODES) g_rowptr[idx] = incl + s_prefix;
}

// ---------------- atomic-free scatter: pos = rowptr[src] + rank ------------
__global__ void k_scatter(const int4* __restrict__ src4,
                          const int4* __restrict__ dst4,
                          const float4* __restrict__ val4) {
    int t = blockIdx.x * blockDim.x + threadIdx.x;
    if (t < NNZ / 4) {
        int4    s = src4[t];
        int4    d = dst4[t];
        float4  v = val4[t];
        ushort4 r = ((const ushort4*)g_rank)[t];
        int p0 = g_rowptr[s.x] + r.x;
        int p1 = g_rowptr[s.y] + r.y;
        int p2 = g_rowptr[s.z] + r.z;
        int p3 = g_rowptr[s.w] + r.w;
        g_edges[p0] = make_int2(d.x, __float_as_int(v.x));
        g_edges[p1] = make_int2(d.y, __float_as_int(v.y));
        g_edges[p2] = make_int2(d.z, __float_as_int(v.z));
        g_edges[p3] = make_int2(d.w, __float_as_int(v.w));
    }
}

// ---------------- SpMM: ONE WARP PER BLOCK, 4 edges/step, uint4 gathers ----
// Lane groups of 8: group g = lane>>3 handles edge (step*4+g); lane loads the
// uint4 (8 halves) at column block (lane&7). fp32 accumulation; next edge
// chunk is prefetched while the current one is processed.
__global__ void __launch_bounds__(32) k_spmm(int layer) {
    const int row  = blockIdx.x;
    const int lane = threadIdx.x;

    const uint4* __restrict__ Xv = (const uint4*)&g_xh[layer - 1][0]; // 8 uint4/row
    uint4* __restrict__ Xout     = (uint4*)&g_xh[layer][0];

    const int col = lane & 7;
    const int grp = lane >> 3;

    int beg = g_rowptr[row];
    int end = g_rowptr[row + 1];
    int len = end - beg;
    int nchunks = len >> 5;
    int rem     = len & 31;

    float a0 = 0.f, a1 = 0.f, a2 = 0.f, a3 = 0.f;
    float a4 = 0.f, a5 = 0.f, a6 = 0.f, a7 = 0.f;

#define SPMM_STEP(EVX, EVY, JIDX)                                            \
    {                                                                        \
        int   dj = __shfl_sync(0xffffffffu, (EVX), (JIDX));                  \
        float vj = __int_as_float(__shfl_sync(0xffffffffu, (EVY), (JIDX))); \
        uint4 q = __ldg(&Xv[dj * 8 + col]);                                  \
        __half2 h0 = *reinterpret_cast<__half2*>(&q.x);                      \
        __half2 h1 = *reinterpret_cast<__half2*>(&q.y);                      \
        __half2 h2 = *reinterpret_cast<__half2*>(&q.z);                      \
        __half2 h3 = *reinterpret_cast<__half2*>(&q.w);                      \
        a0 = fmaf(vj, __low2float(h0),  a0);                                 \
        a1 = fmaf(vj, __high2float(h0), a1);                                 \
        a2 = fmaf(vj, __low2float(h1),  a2);                                 \
        a3 = fmaf(vj, __high2float(h1), a3);                                 \
        a4 = fmaf(vj, __low2float(h2),  a4);                                 \
        a5 = fmaf(vj, __high2float(h2), a5);                                 \
        a6 = fmaf(vj, __low2float(h3),  a6);                                 \
        a7 = fmaf(vj, __high2float(h3), a7);                                 \
    }

    int2 ev;
    if (nchunks > 0) {
        ev = g_edges[beg + lane];                       // first chunk
        int e = beg;
        for (int c = 0; c < nchunks; c++) {
            int2 cur = ev;
            int next = e + 32;
            if (c + 1 < nchunks) {
                ev = g_edges[next + lane];              // prefetch full chunk
            } else {
                ev = (lane < rem) ? g_edges[next + lane] : make_int2(0, 0);
            }
            e = next;
#pragma unroll
            for (int s = 0; s < 8; s++)
                SPMM_STEP(cur.x, cur.y, s * 4 + grp)
        }
    } else {
        ev = (lane < rem) ? g_edges[beg + lane] : make_int2(0, 0);
    }

    // tail: rem edges live in ev
    if (rem > 0) {
        int nsteps = (rem + 3) >> 2;
        for (int s = 0; s < nsteps; s++) {
            int jidx = s * 4 + grp;
            int dj = __shfl_sync(0xffffffffu, ev.x, jidx);
            int vb = __shfl_sync(0xffffffffu, ev.y, jidx);
            if (jidx >= rem) { dj = 0; vb = 0; }
            float vj = __int_as_float(vb);
            uint4 q = __ldg(&Xv[dj * 8 + col]);
            __half2 h0 = *reinterpret_cast<__half2*>(&q.x);
            __half2 h1 = *reinterpret_cast<__half2*>(&q.y);
            __half2 h2 = *reinterpret_cast<__half2*>(&q.z);
            __half2 h3 = *reinterpret_cast<__half2*>(&q.w);
            a0 = fmaf(vj, __low2float(h0),  a0);
            a1 = fmaf(vj, __high2float(h0), a1);
            a2 = fmaf(vj, __low2float(h1),  a2);
            a3 = fmaf(vj, __high2float(h1), a3);
            a4 = fmaf(vj, __low2float(h2),  a4);
            a5 = fmaf(vj, __high2float(h2), a5);
            a6 = fmaf(vj, __low2float(h3),  a6);
            a7 = fmaf(vj, __high2float(h3), a7);
        }
    }
#undef SPMM_STEP

    // reduce the 4 lane-groups (xor 8, then xor 16)
#pragma unroll
    for (int off = 8; off <= 16; off <<= 1) {
        a0 += __shfl_xor_sync(0xffffffffu, a0, off);
        a1 += __shfl_xor_sync(0xffffffffu, a1, off);
        a2 += __shfl_xor_sync(0xffffffffu, a2, off);
        a3 += __shfl_xor_sync(0xffffffffu, a3, off);
        a4 += __shfl_xor_sync(0xffffffffu, a4, off);
        a5 += __shfl_xor_sync(0xffffffffu, a5, off);
        a6 += __shfl_xor_sync(0xffffffffu, a6, off);
        a7 += __shfl_xor_sync(0xffffffffu, a7, off);
    }

    if (lane < 8) {
        __half2 o0 = __floats2half2_rn(a0, a1);
        __half2 o1 = __floats2half2_rn(a2, a3);
        __half2 o2 = __floats2half2_rn(a4, a5);
        __half2 o3 = __floats2half2_rn(a6, a7);
        uint4 o;
        o.x = *reinterpret_cast<unsigned int*>(&o0);
        o.y = *reinterpret_cast<unsigned int*>(&o1);
        o.z = *reinterpret_cast<unsigned int*>(&o2);
        o.w = *reinterpret_cast<unsigned int*>(&o3);
        Xout[row * 8 + lane] = o;
    }
}

// ---------------- final scores: one warp per pair --------------------------
__global__ void k_score(const int* __restrict__ users,
                        const int* __restrict__ items,
                        const float2* __restrict__ user_emb,
                        const float2* __restrict__ item_emb,
                        float* __restrict__ out) {
    const int pair = (blockIdx.x * blockDim.x + threadIdx.x) >> 5;
    const int lane = threadIdx.x & 31;
    if (pair >= BATCH) return;

    int u  = users[pair];
    int it = items[pair];
    int urow = u;
    int irow = N_USERS + it;

    float2 au = user_emb[u * 32 + lane];
    float2 ai = item_emb[it * 32 + lane];
#pragma unroll
    for (int l = 1; l <= N_LAYERS; l++) {
        const __half2* __restrict__ X = (const __half2*)&g_xh[l][0];
        float2 xu = __half22float2(X[urow * 32 + lane]);
        float2 xi = __half22float2(X[irow * 32 + lane]);
        au.x += xu.x; au.y += xu.y;
        ai.x += xi.x; ai.y += xi.y;
    }

    float s = au.x * ai.x + au.y * ai.y;
#pragma unroll
    for (int off = 16; off > 0; off >>= 1)
        s += __shfl_xor_sync(0xffffffffu, s, off);
    if (lane == 0) out[pair] = s * (1.0f / 16.0f);
}

// ---------------- cleanup: restore zeroed state for next call --------------
__global__ void k_cleanup() {
    int i = blockIdx.x * blockDim.x + threadIdx.x;
    if (i <= NNODES) g_rowptr[i] = 0;
    if (i < SCAN_BLOCKS) g_scan_pkt[i] = 0ull;
}

// ---------------- launch ----------------
extern "C" void kernel_launch(void* const* d_in, const int* in_sizes, int n_in,
                              void* d_out, int out_size) {
    const float* user_emb  = (const float*)d_in[0];
    const float* item_emb  = (const float*)d_in[1];
    const float* graph_val = (const float*)d_in[2];
    const int*   graph_src = (const int*)d_in[3];
    const int*   graph_dst = (const int*)d_in[4];
    const int*   users     = (const int*)d_in[5];
    const int*   items     = (const int*)d_in[6];
    float* out = (float*)d_out;

    // launch 0: fused histogram(+ranks) and x0->fp16 init
    k_hist_init<<<(HIST_T + INIT_T + 255) / 256, 256>>>(
        (const int4*)graph_src, (const float4*)user_emb, (const float4*)item_emb);

    // launch 1: single-pass scan (decoupled lookback)
    k_scan<<<SCAN_BLOCKS, 1024>>>();

    // launch 2: scatter into CSR order
    k_scatter<<<(NNZ / 4 + 255) / 256, 256>>>((const int4*)graph_src,
                                              (const int4*)graph_dst,
                                              (const float4*)graph_val);

    // launches 3-5: propagation layers (one warp per row, 1-warp blocks)
    for (int l = 1; l <= N_LAYERS; l++)
        k_spmm<<<NNODES, 32>>>(l);

    // launch 6: scores
    k_score<<<(BATCH + 7) / 8, 256>>>(users, items,
                                      (const float2*)user_emb,
                                      (const float2*)item_emb, out);

    // launch 7: re-zero counters/flags for the next call
    k_cleanup<<<(NNODES + 1 + 255) / 256, 256>>>();
}